// round 7
// baseline (speedup 1.0000x reference)
#include <cuda_runtime.h>

// Problem constants (fixed by setup_inputs: B=32, NT=32, NP=8192)
// Total float4 count: 32*32*8192*3/4 = 6,291,456 ; slab (b,t) = 6144 f4.
#define THREADS 256
#define WARPS 8
#define CHUNK_F4 64            // one 256-bit warp op: 32 lanes * 2 float4
#define CHUNKS_PER_WARP 4
#define GRID 3072              // 3072*8 warps * 4 chunks * 64 f4 = 6,291,456
// warp covers 256 f4; 6144/256 = 24 warps per slab (exact)

#define FULL 0xFFFFFFFFu

// 256-bit global load/store (sm_100a native)
__device__ __forceinline__ void ldg256(const float4* p, float4& x, float4& y) {
    unsigned r0,r1,r2,r3,r4,r5,r6,r7;
    asm("ld.global.nc.v8.b32 {%0,%1,%2,%3,%4,%5,%6,%7}, [%8];"
        : "=r"(r0),"=r"(r1),"=r"(r2),"=r"(r3),
          "=r"(r4),"=r"(r5),"=r"(r6),"=r"(r7) : "l"(p));
    x.x=__uint_as_float(r0); x.y=__uint_as_float(r1);
    x.z=__uint_as_float(r2); x.w=__uint_as_float(r3);
    y.x=__uint_as_float(r4); y.y=__uint_as_float(r5);
    y.z=__uint_as_float(r6); y.w=__uint_as_float(r7);
}
__device__ __forceinline__ void stg256(float4* p, const float4& x, const float4& y) {
    asm volatile("st.global.v8.b32 [%0], {%1,%2,%3,%4,%5,%6,%7,%8};"
        :: "l"(p),
           "r"(__float_as_uint(x.x)), "r"(__float_as_uint(x.y)),
           "r"(__float_as_uint(x.z)), "r"(__float_as_uint(x.w)),
           "r"(__float_as_uint(y.x)), "r"(__float_as_uint(y.y)),
           "r"(__float_as_uint(y.z)), "r"(__float_as_uint(y.w)) : "memory");
}

__global__ __launch_bounds__(THREADS) void fused_xform_kernel(
    const float4* __restrict__ X, const float* __restrict__ dof,
    float4* __restrict__ out)
{
    const int w  = threadIdx.x >> 5;
    const int l  = threadIdx.x & 31;
    const int gw = blockIdx.x * WARPS + w;   // global warp id, 0..24575
    const int slab = gw / 24;                // 24 warps per slab

    // ---- per-slab SE(3) exp (redundant across lanes) ----
    const float* dd = dof + slab * 6;
    float vx = dd[0], vy = dd[1], vz = dd[2];
    float wx = dd[3], wy = dd[4], wz = dd[5];
    float t2 = wx*wx + wy*wy + wz*wz;
    float th = sqrtf(t2);
    float A, B, C;
    if (th < 1e-4f) {
        A = 1.0f - t2 * (1.0f/6.0f);
        B = 0.5f - t2 * (1.0f/24.0f);
        C = (1.0f/6.0f) - t2 * (1.0f/120.0f);
    } else {
        float s, c;
        sincosf(th, &s, &c);
        A = s / th;
        B = (1.0f - c) / t2;
        C = (th - s) / (t2 * th);
    }
    const float r00 = 1.0f + B*(wx*wx - t2);
    const float r01 = -A*wz + B*wx*wy;
    const float r02 =  A*wy + B*wx*wz;
    const float r10 =  A*wz + B*wx*wy;
    const float r11 = 1.0f + B*(wy*wy - t2);
    const float r12 = -A*wx + B*wy*wz;
    const float r20 = -A*wy + B*wx*wz;
    const float r21 =  A*wx + B*wy*wz;
    const float r22 = 1.0f + B*(wz*wz - t2);

    const float v00 = 1.0f + C*(wx*wx - t2);
    const float v01 = -B*wz + C*wx*wy;
    const float v02 =  B*wy + C*wx*wz;
    const float v10 =  B*wz + C*wx*wy;
    const float v11 = 1.0f + C*(wy*wy - t2);
    const float v12 = -B*wx + C*wy*wz;
    const float v20 = -B*wy + C*wx*wz;
    const float v21 =  B*wx + C*wy*wz;
    const float v22 = 1.0f + C*(wz*wz - t2);

    const float tx = v00*vx + v01*vy + v02*vz;
    const float ty = v10*vx + v11*vy + v12*vz;
    const float tz = v20*vx + v21*vy + v22*vz;

    const long wbase = (long)gw * (CHUNKS_PER_WARP * CHUNK_F4);  // first f4 of warp

    // phase of global f4 index k is k % 3 (slab = 6144 f4 ≡ 0 mod 3, so slab-consistent)
    // phase of wbase = (256*gw) % 3 = gw % 3 ; phase of wbase+255 also = gw % 3.
    const int phw = gw % 3;

    // warp-edge neighbor values (rare cross-warp f4s; uniform loads, L2-hot)
    float hz = 0.f, hw = 0.f, tnx = 0.f, tny = 0.f;
    if (phw != 0) { float4 h = X[wbase - 1];  hz = h.z; hw = h.w; }   // gw=0 has phw==0
    if (phw != 2) { float4 t4 = X[wbase + 256]; tnx = t4.x; tny = t4.y; } // last warp has phw==2

    // carry: prev f4 (.z,.w) entering lane 0 of the current chunk
    float cz = hz, cw = hw;

    // prefetch chunk 0: lane holds f4 (2l, 2l+1)
    float4 a, b;
    ldg256(&X[wbase + 2 * l], a, b);

    #pragma unroll
    for (int c = 0; c < CHUNKS_PER_WARP; c++) {
        const long k0 = wbase + (long)c * CHUNK_F4;

        float4 na, nb;
        if (c + 1 < CHUNKS_PER_WARP)
            ldg256(&X[k0 + CHUNK_F4 + 2 * l], na, nb);   // overlaps compute

        // neighbors:
        //  f4 'a' (idx k0+2l): prev = lane l-1's b.zw (lane0 -> carry); next = b.xy (intra-lane)
        //  f4 'b' (idx k0+2l+1): prev = a.zw (intra-lane); next = lane l+1's a.xy (lane31 -> chunk+1)
        float apz = __shfl_up_sync(FULL, b.z, 1);
        float apw = __shfl_up_sync(FULL, b.w, 1);
        if (l == 0) { apz = cz; apw = cw; }
        float bnx = __shfl_down_sync(FULL, a.x, 1);
        float bny = __shfl_down_sync(FULL, a.y, 1);
        float n31x, n31y;
        if (c + 1 < CHUNKS_PER_WARP) {
            n31x = __shfl_sync(FULL, na.x, 0);
            n31y = __shfl_sync(FULL, na.y, 0);
        } else { n31x = tnx; n31y = tny; }
        if (l == 31) { bnx = n31x; bny = n31y; }

        // carry for next chunk: this chunk's last f4 (lane31's b) .z,.w
        cz = __shfl_sync(FULL, b.z, 31);
        cw = __shfl_sync(FULL, b.w, 31);

        const int pa = (phw + c * 64 + 2 * l) % 3;       // phase of f4 'a'
        const int pb = (pa == 2) ? 0 : pa + 1;           // phase of f4 'b'

        float4 oa, ob;
        {   // transform f4 'a'
            const bool is0 = (pa == 0), is1 = (pa == 1);
            const float Fx = is0 ? a.x : (is1 ? apw : apz);
            const float Fy = is0 ? a.y : (is1 ? a.x : apw);
            const float Fz = is0 ? a.z : (is1 ? a.y : a.x);
            const float Sx = is0 ? a.w : (is1 ? a.z : a.y);
            const float Sy = is0 ? b.x : (is1 ? a.w : a.z);
            const float Sz = is0 ? b.y : (is1 ? b.x : a.w);
            const float qFx = fmaf(r00, Fx, fmaf(r01, Fy, fmaf(r02, Fz, tx)));
            const float qFy = fmaf(r10, Fx, fmaf(r11, Fy, fmaf(r12, Fz, ty)));
            const float qFz = fmaf(r20, Fx, fmaf(r21, Fy, fmaf(r22, Fz, tz)));
            const float qSx = fmaf(r00, Sx, fmaf(r01, Sy, fmaf(r02, Sz, tx)));
            const float qSy = fmaf(r10, Sx, fmaf(r11, Sy, fmaf(r12, Sz, ty)));
            const float qSz = fmaf(r20, Sx, fmaf(r21, Sy, fmaf(r22, Sz, tz)));
            oa.x = is0 ? qFx : (is1 ? qFy : qFz);
            oa.y = is0 ? qFy : (is1 ? qFz : qSx);
            oa.z = is0 ? qFz : (is1 ? qSx : qSy);
            oa.w = is0 ? qSx : (is1 ? qSy : qSz);
        }
        {   // transform f4 'b'
            const bool is0 = (pb == 0), is1 = (pb == 1);
            const float Fx = is0 ? b.x : (is1 ? a.w : a.z);
            const float Fy = is0 ? b.y : (is1 ? b.x : a.w);
            const float Fz = is0 ? b.z : (is1 ? b.y : b.x);
            const float Sx = is0 ? b.w : (is1 ? b.z : b.y);
            const float Sy = is0 ? bnx : (is1 ? b.w : b.z);
            const float Sz = is0 ? bny : (is1 ? bnx : b.w);
            const float qFx = fmaf(r00, Fx, fmaf(r01, Fy, fmaf(r02, Fz, tx)));
            const float qFy = fmaf(r10, Fx, fmaf(r11, Fy, fmaf(r12, Fz, ty)));
            const float qFz = fmaf(r20, Fx, fmaf(r21, Fy, fmaf(r22, Fz, tz)));
            const float qSx = fmaf(r00, Sx, fmaf(r01, Sy, fmaf(r02, Sz, tx)));
            const float qSy = fmaf(r10, Sx, fmaf(r11, Sy, fmaf(r12, Sz, ty)));
            const float qSz = fmaf(r20, Sx, fmaf(r21, Sy, fmaf(r22, Sz, tz)));
            ob.x = is0 ? qFx : (is1 ? qFy : qFz);
            ob.y = is0 ? qFy : (is1 ? qFz : qSx);
            ob.z = is0 ? qFz : (is1 ? qSx : qSy);
            ob.w = is0 ? qSx : (is1 ? qSy : qSz);
        }

        stg256(&out[k0 + 2 * l], oa, ob);

        a = na; b = nb;
    }
}

extern "C" void kernel_launch(void* const* d_in, const int* in_sizes, int n_in,
                              void* d_out, int out_size) {
    const float4* X   = (const float4*)d_in[0];   // X_v: 32*32*8192*3 f32
    const float*  dof = (const float*)d_in[1];    // dof: 32*32*6 f32
    float4* out = (float4*)d_out;

    fused_xform_kernel<<<GRID, THREADS>>>(X, dof, out);
}

// round 8
// speedup vs baseline: 1.0931x; 1.0931x over previous
#include <cuda_runtime.h>
#include <cstdint>

// Problem constants (fixed by setup_inputs: B=32, NT=32, NP=8192)
// Total f4 = 32*32*8192*3/4 = 6,291,456 ; slab (b,t) = 6144 f4 = 8 tiles.
#define THREADS 256
#define TILE_F4 768            // 12288 B, = 256 threads * 3 f4 (4 whole points/thread)
#define TILE_BYTES 12288
#define TPB 2                  // tiles per block (both in one slab: blk covers tiles 2b,2b+1)
#define GRID 4096              // 4096 * 2 * 768 = 6,291,456 f4 (exact)

__device__ __forceinline__ uint32_t smem_u32(const void* p) {
    return (uint32_t)__cvta_generic_to_shared(p);
}
__device__ __forceinline__ void mbar_init(uint32_t a, uint32_t cnt) {
    asm volatile("mbarrier.init.shared.b64 [%0], %1;" :: "r"(a), "r"(cnt) : "memory");
}
__device__ __forceinline__ void mbar_expect_tx(uint32_t a, uint32_t bytes) {
    asm volatile("mbarrier.arrive.expect_tx.shared.b64 _, [%0], %1;"
                 :: "r"(a), "r"(bytes) : "memory");
}
__device__ __forceinline__ void bulk_g2s(uint32_t dst, const void* src,
                                         uint32_t bytes, uint32_t mbar) {
    asm volatile("cp.async.bulk.shared::cta.global.mbarrier::complete_tx::bytes "
                 "[%0], [%1], %2, [%3];"
                 :: "r"(dst), "l"(src), "r"(bytes), "r"(mbar) : "memory");
}
__device__ __forceinline__ void bulk_s2g(void* dst, uint32_t src, uint32_t bytes) {
    asm volatile("cp.async.bulk.global.shared::cta.bulk_group [%0], [%1], %2;"
                 :: "l"(dst), "r"(src), "r"(bytes) : "memory");
}
__device__ __forceinline__ void bulk_commit() {
    asm volatile("cp.async.bulk.commit_group;" ::: "memory");
}
__device__ __forceinline__ void bulk_wait_all() {
    asm volatile("cp.async.bulk.wait_group 0;" ::: "memory");
}
__device__ __forceinline__ void fence_async_shared() {
    asm volatile("fence.proxy.async.shared::cta;" ::: "memory");
}
__device__ __forceinline__ void mbar_wait_parity(uint32_t a, uint32_t parity) {
    asm volatile(
        "{\n\t"
        ".reg .pred P;\n\t"
        "WL_%=:\n\t"
        "mbarrier.try_wait.parity.acquire.cta.shared::cta.b64 P, [%0], %1, 0x989680;\n\t"
        "@P bra WD_%=;\n\t"
        "bra.uni WL_%=;\n\t"
        "WD_%=:\n\t"
        "}"
        :: "r"(a), "r"(parity) : "memory");
}

__global__ __launch_bounds__(THREADS, 5) void fused_xform_kernel(
    const float4* __restrict__ X, const float* __restrict__ dof,
    float4* __restrict__ out)
{
    __shared__ __align__(16) float4 buf[TPB][TILE_F4];
    __shared__ unsigned long long mbar[TPB];

    const int tid  = threadIdx.x;
    const int blk  = blockIdx.x;
    const int slab = blk >> 2;                 // 4 blocks per slab

    const uint32_t mb0 = smem_u32(&mbar[0]);
    const uint32_t mb1 = smem_u32(&mbar[1]);

    // ---- kick off both tile loads immediately (engine-held MLP) ----
    if (tid == 0) {
        mbar_init(mb0, 1);
        mbar_init(mb1, 1);
        fence_async_shared();
    }
    __syncthreads();
    if (tid == 0) {
        const long gbase = (long)blk * (TPB * TILE_F4);
        mbar_expect_tx(mb0, TILE_BYTES);
        bulk_g2s(smem_u32(&buf[0][0]), &X[gbase], TILE_BYTES, mb0);
        mbar_expect_tx(mb1, TILE_BYTES);
        bulk_g2s(smem_u32(&buf[1][0]), &X[gbase + TILE_F4], TILE_BYTES, mb1);
    }

    // ---- per-slab SE(3) exp (all threads, overlaps the TMA latency) ----
    const float* dd = dof + slab * 6;
    float vx = dd[0], vy = dd[1], vz = dd[2];
    float wx = dd[3], wy = dd[4], wz = dd[5];
    float t2 = wx*wx + wy*wy + wz*wz;
    float th = sqrtf(t2);
    float A, B, C;
    if (th < 1e-4f) {
        A = 1.0f - t2 * (1.0f/6.0f);
        B = 0.5f - t2 * (1.0f/24.0f);
        C = (1.0f/6.0f) - t2 * (1.0f/120.0f);
    } else {
        float s, c;
        sincosf(th, &s, &c);
        A = s / th;
        B = (1.0f - c) / t2;
        C = (th - s) / (t2 * th);
    }
    // K^2 = w w^T - t2*I
    const float r00 = 1.0f + B*(wx*wx - t2);
    const float r01 = -A*wz + B*wx*wy;
    const float r02 =  A*wy + B*wx*wz;
    const float r10 =  A*wz + B*wx*wy;
    const float r11 = 1.0f + B*(wy*wy - t2);
    const float r12 = -A*wx + B*wy*wz;
    const float r20 = -A*wy + B*wx*wz;
    const float r21 =  A*wx + B*wy*wz;
    const float r22 = 1.0f + B*(wz*wz - t2);

    const float v00 = 1.0f + C*(wx*wx - t2);
    const float v01 = -B*wz + C*wx*wy;
    const float v02 =  B*wy + C*wx*wz;
    const float v10 =  B*wz + C*wx*wy;
    const float v11 = 1.0f + C*(wy*wy - t2);
    const float v12 = -B*wx + C*wy*wz;
    const float v20 = -B*wy + C*wx*wz;
    const float v21 =  B*wx + C*wy*wz;
    const float v22 = 1.0f + C*(wz*wz - t2);

    const float tx = v00*vx + v01*vy + v02*vz;
    const float ty = v10*vx + v11*vy + v12*vz;
    const float tz = v20*vx + v21*vy + v22*vz;

    // ---- two tiles: wait -> transform in place -> bulk store ----
    #pragma unroll
    for (int it = 0; it < TPB; it++) {
        mbar_wait_parity(it == 0 ? mb0 : mb1, 0);

        // lane owns f4 slots 3*tid..3*tid+2 = 4 whole points (self-contained)
        float4 a = buf[it][3 * tid + 0];
        float4 b = buf[it][3 * tid + 1];
        float4 c = buf[it][3 * tid + 2];

        // p0=(a.x,a.y,a.z) p1=(a.w,b.x,b.y) p2=(b.z,b.w,c.x) p3=(c.y,c.z,c.w)
        float ox0 = fmaf(r00, a.x, fmaf(r01, a.y, fmaf(r02, a.z, tx)));
        float oy0 = fmaf(r10, a.x, fmaf(r11, a.y, fmaf(r12, a.z, ty)));
        float oz0 = fmaf(r20, a.x, fmaf(r21, a.y, fmaf(r22, a.z, tz)));

        float ox1 = fmaf(r00, a.w, fmaf(r01, b.x, fmaf(r02, b.y, tx)));
        float oy1 = fmaf(r10, a.w, fmaf(r11, b.x, fmaf(r12, b.y, ty)));
        float oz1 = fmaf(r20, a.w, fmaf(r21, b.x, fmaf(r22, b.y, tz)));

        float ox2 = fmaf(r00, b.z, fmaf(r01, b.w, fmaf(r02, c.x, tx)));
        float oy2 = fmaf(r10, b.z, fmaf(r11, b.w, fmaf(r12, c.x, ty)));
        float oz2 = fmaf(r20, b.z, fmaf(r21, b.w, fmaf(r22, c.x, tz)));

        float ox3 = fmaf(r00, c.y, fmaf(r01, c.z, fmaf(r02, c.w, tx)));
        float oy3 = fmaf(r10, c.y, fmaf(r11, c.z, fmaf(r12, c.w, ty)));
        float oz3 = fmaf(r20, c.y, fmaf(r21, c.z, fmaf(r22, c.w, tz)));

        // overwrite own slots (no cross-thread hazard)
        buf[it][3 * tid + 0] = make_float4(ox0, oy0, oz0, ox1);
        buf[it][3 * tid + 1] = make_float4(oy1, oz1, ox2, oy2);
        buf[it][3 * tid + 2] = make_float4(oz2, ox3, oy3, oz3);

        __syncthreads();          // all lanes' results in smem
        if (tid == 0) {
            fence_async_shared(); // order generic STS before async-proxy read
            bulk_s2g(&out[(long)blk * (TPB * TILE_F4) + (long)it * TILE_F4],
                     smem_u32(&buf[it][0]), TILE_BYTES);
            bulk_commit();
        }
    }

    // keep CTA alive until bulk stores have read smem
    if (tid == 0) bulk_wait_all();
}

extern "C" void kernel_launch(void* const* d_in, const int* in_sizes, int n_in,
                              void* d_out, int out_size) {
    const float4* X   = (const float4*)d_in[0];   // X_v: 32*32*8192*3 f32
    const float*  dof = (const float*)d_in[1];    // dof: 32*32*6 f32
    float4* out = (float4*)d_out;

    fused_xform_kernel<<<GRID, THREADS>>>(X, dof, out);
}